// round 1
// baseline (speedup 1.0000x reference)
#include <cuda_runtime.h>
#include <cstdint>
#include <cstddef>

#define BATCH 8
#define SEQ   2048
#define HID   256
#define INDIM 96
#define NKT   (SEQ / 128)   // 16 key tiles in score kernel

// ---------------- scratch (device globals: allocation-free rule) ----------------
__device__ float g_q[BATCH * SEQ * HID];
__device__ float g_k[BATCH * SEQ * HID];
__device__ float g_v[BATCH * SEQ * HID];
__device__ float g_p[(size_t)BATCH * SEQ * SEQ];           // exp(masked score), unnormalized
__device__ float g_rpart[NKT * BATCH * SEQ];               // per-ktile row-sum partials

// ---------------- helpers ----------------
__device__ __forceinline__ unsigned f2tf32(float x) {
    unsigned r;
    asm("cvt.rna.tf32.f32 %0, %1;" : "=r"(r) : "f"(x));
    return r;
}

__device__ __forceinline__ void mma_tf32(float c[4], const unsigned a[4], const unsigned b[2]) {
    asm("mma.sync.aligned.m16n8k8.row.col.f32.tf32.tf32.f32 "
        "{%0,%1,%2,%3}, {%4,%5,%6,%7}, {%8,%9}, {%0,%1,%2,%3};\n"
        : "+f"(c[0]), "+f"(c[1]), "+f"(c[2]), "+f"(c[3])
        : "r"(a[0]), "r"(a[1]), "r"(a[2]), "r"(a[3]), "r"(b[0]), "r"(b[1]));
}

__device__ __forceinline__ unsigned long long pack2(float lo, float hi) {
    unsigned long long r;
    asm("mov.b64 %0, {%1, %2};" : "=l"(r) : "f"(lo), "f"(hi));
    return r;
}
__device__ __forceinline__ void unpack2(unsigned long long p, float& lo, float& hi) {
    asm("mov.b64 {%0, %1}, %2;" : "=f"(lo), "=f"(hi) : "l"(p));
}
__device__ __forceinline__ void ffma2(unsigned long long& d, unsigned long long a, unsigned long long b) {
    asm("fma.rn.f32x2 %0, %1, %2, %0;" : "+l"(d) : "l"(a), "l"(b));
}

// ---------------- kernel 1: projections (fp32, f32x2 FMA) ----------------
// grid (BATCH*SEQ/16, 3), block 256. Each block: 16 rows x 256 cols, K=96.
__global__ void __launch_bounds__(256) proj_kernel(
    const float* __restrict__ xq, const float* __restrict__ xk, const float* __restrict__ xv,
    const float* __restrict__ Wq, const float* __restrict__ bq,
    const float* __restrict__ Wk, const float* __restrict__ bk,
    const float* __restrict__ Wv, const float* __restrict__ bv)
{
    const int proj = blockIdx.y;
    const float* x; const float* W; const float* bias; float* o;
    if (proj == 0)      { x = xq; W = Wq; bias = bq; o = g_q; }
    else if (proj == 1) { x = xk; W = Wk; bias = bk; o = g_k; }
    else                { x = xv; W = Wv; bias = bv; o = g_v; }

    const int row0 = blockIdx.x * 16;
    __shared__ float xs[INDIM * 16];   // xs[f*16 + r]: row pairs adjacent for b64 reads
    const int tid = threadIdx.x;

    for (int i = tid; i < 16 * INDIM; i += 256) {
        int r = i / INDIM, f = i - r * INDIM;
        xs[f * 16 + r] = x[(size_t)(row0 + r) * INDIM + f];
    }
    __syncthreads();

    const int h = tid;               // 256 threads = 256 output cols
    const float bh = bias[h];
    unsigned long long acc[8];
#pragma unroll
    for (int j = 0; j < 8; j++) acc[j] = pack2(bh, bh);

#pragma unroll 4
    for (int f = 0; f < INDIM; f++) {
        float w = W[f * HID + h];
        unsigned long long w2 = pack2(w, w);
        const unsigned long long* xp = (const unsigned long long*)(xs + f * 16);
#pragma unroll
        for (int j = 0; j < 8; j++) ffma2(acc[j], xp[j], w2);
    }
#pragma unroll
    for (int j = 0; j < 8; j++) {
        float a, b;
        unpack2(acc[j], a, b);
        o[(size_t)(row0 + 2 * j)     * HID + h] = a;
        o[(size_t)(row0 + 2 * j + 1) * HID + h] = b;
    }
}

// ---------------- kernel 2: scores -> exp(masked) + row-sum partials ----------------
// grid (16 ktile, 16 qtile, 8 batch), block 256 (8 warps, 4x2 warp grid).
// Block tile: 128(q) x 128(k), K = 256, tf32 MMA.
__global__ void __launch_bounds__(256) score_kernel(const int* __restrict__ mask)
{
    const int kt = blockIdx.x, qt = blockIdx.y, b = blockIdx.z;
    const float* Qg = g_q + ((size_t)b * SEQ + qt * 128) * HID;
    const float* Kg = g_k + ((size_t)b * SEQ + kt * 128) * HID;

    __shared__ unsigned Qs[128 * 36];
    __shared__ unsigned Ks[128 * 36];
    __shared__ float rsum_sm[2][128];

    const int tid = threadIdx.x;
    const int warp = tid >> 5, lane = tid & 31;
    const int wm = warp & 3, wn = warp >> 2;    // wm: 4 row groups of 32, wn: 2 col groups of 64
    const int tg = lane & 3, gi = lane >> 2;

    float acc[2][8][4];
#pragma unroll
    for (int mi = 0; mi < 2; mi++)
#pragma unroll
        for (int ni = 0; ni < 8; ni++)
#pragma unroll
            for (int c = 0; c < 4; c++) acc[mi][ni][c] = 0.f;

    for (int kc = 0; kc < HID; kc += 32) {
#pragma unroll
        for (int i = 0; i < 4; i++) {
            int idx = tid + i * 256;           // 0..1023 -> 128 rows x 8 float4
            int r = idx >> 3, c4 = (idx & 7) * 4;
            float4 qv = *(const float4*)(Qg + (size_t)r * HID + kc + c4);
            float4 kv = *(const float4*)(Kg + (size_t)r * HID + kc + c4);
            unsigned* qd = &Qs[r * 36 + c4];
            qd[0] = f2tf32(qv.x); qd[1] = f2tf32(qv.y); qd[2] = f2tf32(qv.z); qd[3] = f2tf32(qv.w);
            unsigned* kd = &Ks[r * 36 + c4];
            kd[0] = f2tf32(kv.x); kd[1] = f2tf32(kv.y); kd[2] = f2tf32(kv.z); kd[3] = f2tf32(kv.w);
        }
        __syncthreads();
#pragma unroll
        for (int ks = 0; ks < 32; ks += 8) {
            unsigned af[2][4], bf[8][2];
#pragma unroll
            for (int mi = 0; mi < 2; mi++) {
                int r = wm * 32 + mi * 16 + gi;
                af[mi][0] = Qs[r * 36 + ks + tg];
                af[mi][1] = Qs[(r + 8) * 36 + ks + tg];
                af[mi][2] = Qs[r * 36 + ks + tg + 4];
                af[mi][3] = Qs[(r + 8) * 36 + ks + tg + 4];
            }
#pragma unroll
            for (int ni = 0; ni < 8; ni++) {
                int n = wn * 64 + ni * 8 + gi;
                bf[ni][0] = Ks[n * 36 + ks + tg];
                bf[ni][1] = Ks[n * 36 + ks + tg + 4];
            }
#pragma unroll
            for (int mi = 0; mi < 2; mi++)
#pragma unroll
                for (int ni = 0; ni < 8; ni++)
                    mma_tf32(acc[mi][ni], af[mi], bf[ni]);
        }
        __syncthreads();
    }

    // epilogue: scale, mask, exp, write P, deterministic row-sum partials
    const float scale = 0.0625f;   // 1/sqrt(256)
#pragma unroll
    for (int mi = 0; mi < 2; mi++) {
        int r0 = qt * 128 + wm * 32 + mi * 16 + gi;   // q row within batch
        int r1 = r0 + 8;
        size_t base0 = ((size_t)b * SEQ + r0) * SEQ;
        size_t base1 = ((size_t)b * SEQ + r1) * SEQ;
        float rs0 = 0.f, rs1 = 0.f;
#pragma unroll
        for (int ni = 0; ni < 8; ni++) {
            int c0 = kt * 128 + wn * 64 + ni * 8 + tg * 2;
            int2 m0 = *(const int2*)(mask + base0 + c0);
            int2 m1 = *(const int2*)(mask + base1 + c0);
            float p00 = m0.x ? __expf(acc[mi][ni][0] * scale) : 0.f;
            float p01 = m0.y ? __expf(acc[mi][ni][1] * scale) : 0.f;
            float p10 = m1.x ? __expf(acc[mi][ni][2] * scale) : 0.f;
            float p11 = m1.y ? __expf(acc[mi][ni][3] * scale) : 0.f;
            *(float2*)(g_p + base0 + c0) = make_float2(p00, p01);
            *(float2*)(g_p + base1 + c0) = make_float2(p10, p11);
            rs0 += p00 + p01;
            rs1 += p10 + p11;
        }
        rs0 += __shfl_xor_sync(0xffffffffu, rs0, 1);
        rs0 += __shfl_xor_sync(0xffffffffu, rs0, 2);
        rs1 += __shfl_xor_sync(0xffffffffu, rs1, 1);
        rs1 += __shfl_xor_sync(0xffffffffu, rs1, 2);
        if (tg == 0) {
            int rl = wm * 32 + mi * 16 + gi;
            rsum_sm[wn][rl]     = rs0;
            rsum_sm[wn][rl + 8] = rs1;
        }
    }
    __syncthreads();
    if (tid < 128) {
        // one writer per (ktile,row): deterministic
        g_rpart[(size_t)kt * (BATCH * SEQ) + (size_t)b * SEQ + qt * 128 + tid] =
            rsum_sm[0][tid] + rsum_sm[1][tid];
    }
}

// ---------------- kernel 3: O = (P/rowsum) @ V, fused LayerNorm ----------------
// grid (SEQ/64, BATCH), block 256 (8 warps, 2x4 warp grid).
// Block tile: 64(q) x 256(h), K = 2048, tf32 MMA.
__global__ void __launch_bounds__(256) pv_kernel(const float* __restrict__ gamma,
                                                 const float* __restrict__ beta,
                                                 float* __restrict__ out)
{
    const int qs = blockIdx.x;
    const int b  = blockIdx.y;
    const float* Pg = g_p + ((size_t)b * SEQ + qs * 64) * SEQ;
    const float* Vg = g_v + (size_t)b * SEQ * HID;

    __shared__ unsigned Ps[64 * 36];
    __shared__ unsigned Vs[32 * 264];
    __shared__ float rstat[4 * 128];   // [wn][row*2 + {sum,sumsq}]

    const int tid = threadIdx.x;
    const int warp = tid >> 5, lane = tid & 31;
    const int wm = warp & 1, wn = warp >> 1;    // wm: 2 row groups of 32, wn: 4 col groups of 64
    const int tg = lane & 3, gi = lane >> 2;

    float acc[2][8][4];
#pragma unroll
    for (int mi = 0; mi < 2; mi++)
#pragma unroll
        for (int ni = 0; ni < 8; ni++)
#pragma unroll
            for (int c = 0; c < 4; c++) acc[mi][ni][c] = 0.f;

    for (int kc = 0; kc < SEQ; kc += 32) {
#pragma unroll
        for (int i = 0; i < 2; i++) {
            int idx = tid + i * 256;           // 0..511 -> 64 rows x 8 float4
            int r = idx >> 3, c4 = (idx & 7) * 4;
            float4 pv = *(const float4*)(Pg + (size_t)r * SEQ + kc + c4);
            unsigned* d = &Ps[r * 36 + c4];
            d[0] = f2tf32(pv.x); d[1] = f2tf32(pv.y); d[2] = f2tf32(pv.z); d[3] = f2tf32(pv.w);
        }
#pragma unroll
        for (int i = 0; i < 8; i++) {
            int idx = tid + i * 256;           // 0..2047 -> 32 rows x 64 float4
            int r = idx >> 6, c4 = (idx & 63) * 4;
            float4 vv = *(const float4*)(Vg + (size_t)(kc + r) * HID + c4);
            unsigned* d = &Vs[r * 264 + c4];
            d[0] = f2tf32(vv.x); d[1] = f2tf32(vv.y); d[2] = f2tf32(vv.z); d[3] = f2tf32(vv.w);
        }
        __syncthreads();
#pragma unroll
        for (int ks = 0; ks < 32; ks += 8) {
            unsigned af[2][4], bf[8][2];
#pragma unroll
            for (int mi = 0; mi < 2; mi++) {
                int r = wm * 32 + mi * 16 + gi;
                af[mi][0] = Ps[r * 36 + ks + tg];
                af[mi][1] = Ps[(r + 8) * 36 + ks + tg];
                af[mi][2] = Ps[r * 36 + ks + tg + 4];
                af[mi][3] = Ps[(r + 8) * 36 + ks + tg + 4];
            }
#pragma unroll
            for (int ni = 0; ni < 8; ni++) {
                int n = wn * 64 + ni * 8 + gi;
                bf[ni][0] = Vs[(ks + tg) * 264 + n];
                bf[ni][1] = Vs[(ks + tg + 4) * 264 + n];
            }
#pragma unroll
            for (int mi = 0; mi < 2; mi++)
#pragma unroll
                for (int ni = 0; ni < 8; ni++)
                    mma_tf32(acc[mi][ni], af[mi], bf[ni]);
        }
        __syncthreads();
    }

    // ---- normalize by rowsum (deterministic fixed-order sum of 16 partials) ----
#pragma unroll
    for (int mi = 0; mi < 2; mi++) {
        int rl0 = wm * 32 + mi * 16 + gi;
        int rl1 = rl0 + 8;
        size_t rg0 = (size_t)b * SEQ + qs * 64 + rl0;
        size_t rg1 = (size_t)b * SEQ + qs * 64 + rl1;
        float rs0 = 0.f, rs1 = 0.f;
#pragma unroll
        for (int t = 0; t < NKT; t++) {
            rs0 += g_rpart[(size_t)t * (BATCH * SEQ) + rg0];
            rs1 += g_rpart[(size_t)t * (BATCH * SEQ) + rg1];
        }
        float i0 = 1.f / rs0, i1 = 1.f / rs1;
        float s0 = 0.f, s1 = 0.f, q0 = 0.f, q1 = 0.f;
#pragma unroll
        for (int ni = 0; ni < 8; ni++) {
            float v00 = acc[mi][ni][0] * i0; acc[mi][ni][0] = v00;
            float v01 = acc[mi][ni][1] * i0; acc[mi][ni][1] = v01;
            float v10 = acc[mi][ni][2] * i1; acc[mi][ni][2] = v10;
            float v11 = acc[mi][ni][3] * i1; acc[mi][ni][3] = v11;
            s0 += v00 + v01; s1 += v10 + v11;
            q0 += v00 * v00 + v01 * v01;
            q1 += v10 * v10 + v11 * v11;
        }
        s0 += __shfl_xor_sync(0xffffffffu, s0, 1); s0 += __shfl_xor_sync(0xffffffffu, s0, 2);
        s1 += __shfl_xor_sync(0xffffffffu, s1, 1); s1 += __shfl_xor_sync(0xffffffffu, s1, 2);
        q0 += __shfl_xor_sync(0xffffffffu, q0, 1); q0 += __shfl_xor_sync(0xffffffffu, q0, 2);
        q1 += __shfl_xor_sync(0xffffffffu, q1, 1); q1 += __shfl_xor_sync(0xffffffffu, q1, 2);
        if (tg == 0) {
            rstat[wn * 128 + rl0 * 2]     = s0;
            rstat[wn * 128 + rl0 * 2 + 1] = q0;
            rstat[wn * 128 + rl1 * 2]     = s1;
            rstat[wn * 128 + rl1 * 2 + 1] = q1;
        }
    }
    __syncthreads();

    // ---- LayerNorm + write out ----
#pragma unroll
    for (int mi = 0; mi < 2; mi++) {
        int rl0 = wm * 32 + mi * 16 + gi;
        int rl1 = rl0 + 8;
        float sum0 = rstat[rl0 * 2] + rstat[128 + rl0 * 2] + rstat[256 + rl0 * 2] + rstat[384 + rl0 * 2];
        float sq0  = rstat[rl0 * 2 + 1] + rstat[128 + rl0 * 2 + 1] + rstat[256 + rl0 * 2 + 1] + rstat[384 + rl0 * 2 + 1];
        float sum1 = rstat[rl1 * 2] + rstat[128 + rl1 * 2] + rstat[256 + rl1 * 2] + rstat[384 + rl1 * 2];
        float sq1  = rstat[rl1 * 2 + 1] + rstat[128 + rl1 * 2 + 1] + rstat[256 + rl1 * 2 + 1] + rstat[384 + rl1 * 2 + 1];
        float mu0 = sum0 * (1.f / HID);
        float mu1 = sum1 * (1.f / HID);
        float var0 = sq0 * (1.f / HID) - mu0 * mu0;
        float var1 = sq1 * (1.f / HID) - mu1 * mu1;
        float rstd0 = rsqrtf(var0 + 1e-6f);
        float rstd1 = rsqrtf(var1 + 1e-6f);
        size_t orow0 = ((size_t)b * SEQ + qs * 64 + rl0) * HID;
        size_t orow1 = ((size_t)b * SEQ + qs * 64 + rl1) * HID;
#pragma unroll
        for (int ni = 0; ni < 8; ni++) {
            int c0 = wn * 64 + ni * 8 + tg * 2;
            float2 gm = *(const float2*)(gamma + c0);
            float2 bt = *(const float2*)(beta + c0);
            float2 o0, o1;
            o0.x = (acc[mi][ni][0] - mu0) * rstd0 * gm.x + bt.x;
            o0.y = (acc[mi][ni][1] - mu0) * rstd0 * gm.y + bt.y;
            o1.x = (acc[mi][ni][2] - mu1) * rstd1 * gm.x + bt.x;
            o1.y = (acc[mi][ni][3] - mu1) * rstd1 * gm.y + bt.y;
            *(float2*)(out + orow0 + c0) = o0;
            *(float2*)(out + orow1 + c0) = o1;
        }
    }
}

// ---------------- launch ----------------
extern "C" void kernel_launch(void* const* d_in, const int* in_sizes, int n_in,
                              void* d_out, int out_size)
{
    const float* q     = (const float*)d_in[0];
    const float* k     = (const float*)d_in[1];
    const float* v     = (const float*)d_in[2];
    const int*   mask  = (const int*)  d_in[3];
    const float* Wq    = (const float*)d_in[4];
    const float* bq    = (const float*)d_in[5];
    const float* Wk    = (const float*)d_in[6];
    const float* bk    = (const float*)d_in[7];
    const float* Wv    = (const float*)d_in[8];
    const float* bv    = (const float*)d_in[9];
    const float* gamma = (const float*)d_in[10];
    const float* beta  = (const float*)d_in[11];
    float* out = (float*)d_out;

    dim3 gp(BATCH * SEQ / 16, 3);
    proj_kernel<<<gp, 256>>>(q, k, v, Wq, bq, Wk, bk, Wv, bv);

    dim3 gs(SEQ / 128, SEQ / 128, BATCH);
    score_kernel<<<gs, 256>>>(mask);

    dim3 go(SEQ / 64, BATCH);
    pv_kernel<<<go, 256>>>(gamma, beta, out);
}